// round 13
// baseline (speedup 1.0000x reference)
#include <cuda_runtime.h>
#include <cuda_fp16.h>
#include <mma.h>
#include <cstdint>

using namespace nvcuda;

// Problem constants: B=2, Q=KV=2048, D=1024, H=16, DH=64
#define BB     2
#define QQ     2048
#define KVN    2048
#define DD     1024
#define HH     16
#define MROWS  (BB*QQ)
#define EPS_F  1.1920928955078125e-07f

// GEMM tiling (fp16 operands, fp32 accum): 256 thr, 2x4 warps, warp tile 64x32
#define BM 128
#define BN 128
#define BK 64                    // 64 halves = 128B per row slab
#define APAD 72                  // padded row stride in halves
#define NSTAGE 3
#define NTILES (KVN / BN)        // 16 n-tiles for scores lpart

// smem in halves: As[3][128*72] | Bs[3][128*72]; epilogue reuses base as float C[128*128]
#define S_A(buf)  ((buf) * (BM * APAD))
#define S_B(buf)  (NSTAGE * BM * APAD + (buf) * (BN * APAD))
#define SMEM_HALVES (NSTAGE * 2 * BM * APAD)
#define SMEM_BYTES  (SMEM_HALVES * 2)          // 110592

// ---------------- scratch ----------------------------------------------------
__device__ __half g_xn[(size_t)2 * MROWS * DD];    // [0]=qn, [1]=kn
__device__ __half g_Wr[(size_t)2 * DD * DD];       // [0]=Wq, [1]=Wk (fp16)
__device__ float  g_b[2 * DD];                     // [0]=bq, [1]=bk
__device__ __half g_qkp[(size_t)2 * MROWS * DD];   // [0]=qp, [1]=kp
__device__ __half g_vT[(size_t)BB * DD * KVN];
__device__ __half g_scores[(size_t)BB * HH * QQ * KVN];   // exp(s/8), fp16 (268MB)
__device__ float  g_lpart[(size_t)BB * HH * QQ * NTILES]; // per-n-tile row sums
__device__ __half g_attn[(size_t)BB * QQ * KVN];

// ---------------- helpers ----------------------------------------------------
__device__ __forceinline__ uint32_t smem_u32(const void* p) {
    uint32_t a;
    asm("{ .reg .u64 t; cvta.to.shared.u64 t, %1; cvt.u32.u64 %0, t; }" : "=r"(a) : "l"(p));
    return a;
}
#define CP_ASYNC16(dst_u32, src_ptr) \
    asm volatile("cp.async.ca.shared.global [%0], [%1], 16;" :: "r"(dst_u32), "l"(src_ptr))
#define CP_COMMIT() asm volatile("cp.async.commit_group;")
#define CP_WAIT2()  asm volatile("cp.async.wait_group 2;")
#define CP_WAIT1()  asm volatile("cp.async.wait_group 1;")
#define CP_WAIT0()  asm volatile("cp.async.wait_group 0;")

__device__ __forceinline__ uint32_t pack2(float a, float b) {
    __half2 h = __floats2half2_rn(a, b);
    return *reinterpret_cast<uint32_t*>(&h);
}

// ---------------- K: rmsnorm + fold norm-weight -> fp16 ----------------------
__global__ void rmsnorm_fold(const float* __restrict__ q, const float* __restrict__ k,
                             const float* __restrict__ wq, const float* __restrict__ wk) {
    const float* x; const float* w;
    if (blockIdx.y == 0) { x = q; w = wq; } else { x = k; w = wk; }
    __half* o = g_xn + (size_t)blockIdx.y * MROWS * DD;
    size_t row = blockIdx.x;
    int t = threadIdx.x;
    const float* xr = x + row * DD;
    float4 v = *(const float4*)(xr + t * 4);
    float ss = v.x*v.x + v.y*v.y + v.z*v.z + v.w*v.w;
#pragma unroll
    for (int s = 16; s; s >>= 1) ss += __shfl_xor_sync(0xffffffffu, ss, s);
    __shared__ float red[8];
    if ((t & 31) == 0) red[t >> 5] = ss;
    __syncthreads();
    float tot = 0.f;
#pragma unroll
    for (int i = 0; i < 8; ++i) tot += red[i];
    float sc = rsqrtf(tot * (1.0f / (float)DD) + EPS_F);
    float4 wv = *(const float4*)(w + t * 4);
    uint2 pkd;
    pkd.x = pack2(v.x * sc * wv.x, v.y * sc * wv.y);
    pkd.y = pack2(v.z * sc * wv.z, v.w * sc * wv.w);
    *(uint2*)(o + row * DD + t * 4) = pkd;
}

// ---------------- K: weights -> fp16, copy biases -----------------------------
__global__ void wprep(const float* __restrict__ Wq, const float* __restrict__ Wk,
                      const float* __restrict__ bq, const float* __restrict__ bk) {
    int z = blockIdx.y;
    const float* s = z ? Wk : Wq;
    __half* o = g_Wr + (size_t)z * DD * DD;
    size_t i = (size_t)blockIdx.x * 1024 + threadIdx.x * 4;
    float4 v = *(const float4*)(s + i);
    uint2 pkd;
    pkd.x = pack2(v.x, v.y);
    pkd.y = pack2(v.z, v.w);
    *(uint2*)(o + i) = pkd;
    if (blockIdx.x == 0) {
        const float* bs = z ? bk : bq;
        *(float4*)(g_b + z * DD + threadIdx.x * 4) = *(const float4*)(bs + threadIdx.x * 4);
    }
}

// ---------------- K: transpose value -> vT[b][d][j] fp16 ---------------------
__global__ void transpose_v(const float* __restrict__ v) {
    int b = blockIdx.z;
    int j0 = blockIdx.x * 32, d0 = blockIdx.y * 32;
    __shared__ float T[32][33];
    int tx = threadIdx.x, ty = threadIdx.y;
    const float* src = v + ((size_t)b * KVN + j0) * DD + d0;
#pragma unroll
    for (int e = 0; e < 4; ++e)
        T[ty + 8*e][tx] = src[(size_t)(ty + 8*e) * DD + tx];
    __syncthreads();
    __half* dst = g_vT + ((size_t)b * DD + d0) * KVN + j0;
#pragma unroll
    for (int e = 0; e < 4; ++e)
        dst[(size_t)(ty + 8*e) * KVN + tx] = __float2half_rn(T[tx][ty + 8*e]);
}

// ---------------- fp16 wmma GEMM (8 warps, 64x32 tiles, 3-stage pipe) --------
// D[M,N] = f(alpha * A[M,K] @ B[N,K]^T), A/B fp16 row-major, acc fp32
// MODE 0: C = alpha*acc + bias[z*biasStride + n] (optional), OutT = __half or float
// MODE 1 (scores): C = exp(alpha*acc) packed fp16; fp32 row sums -> lpart
template <int MODE, typename OutT>
__global__ void __launch_bounds__(256, 2) gemm_mma(
    const __half* __restrict__ A, const __half* __restrict__ B,
    const float* __restrict__ bias, OutT* __restrict__ C, float* __restrict__ lpart,
    int K, int lda, int ldb, int ldc,
    long aStride, long bStride, long cStride, long biasStride, float alpha) {
    extern __shared__ __half smem[];
    uint32_t sb = smem_u32(smem);
    int t = threadIdx.x, warp = t >> 5;
    int wm = warp >> 2, wn = warp & 3;    // 2 x 4 warp grid; warp tile 64 x 32

    long z = blockIdx.z;
    const __half *Ab, *Bb; OutT* Cb;
    const float* biasb = bias ? bias + z * biasStride : nullptr;
    if (MODE == 1) {
        long b = z >> 4, h = z & 15;
        Ab = A + b * aStride + h * 64;
        Bb = B + b * bStride + h * 64;
        Cb = C + z * cStride;
    } else {
        Ab = A + z * aStride; Bb = B + z * bStride; Cb = C + z * cStride;
    }
    int m0 = blockIdx.y * BM, n0 = blockIdx.x * BN;

    wmma::fragment<wmma::accumulator, 16, 16, 16, float> acc[4][2];
#pragma unroll
    for (int i = 0; i < 4; ++i)
#pragma unroll
        for (int j = 0; j < 2; ++j) wmma::fill_fragment(acc[i][j], 0.0f);

    int r0 = t >> 1;             // row 0..127
    int cb = (t & 1) * 32;       // half-column base (each thread: 4 x 8-half chunks)

    auto issue = [&](int c, int buf) {
        const __half* Ag = Ab + (size_t)(m0 + r0) * lda + c * BK + cb;
        const __half* Bg = Bb + (size_t)(n0 + r0) * ldb + c * BK + cb;
        uint32_t ad = sb + (S_A(buf) + r0 * APAD + cb) * 2;
        uint32_t bd = sb + (S_B(buf) + r0 * APAD + cb) * 2;
#pragma unroll
        for (int l = 0; l < 4; ++l) CP_ASYNC16(ad + l * 16, Ag + l * 8);
#pragma unroll
        for (int l = 0; l < 4; ++l) CP_ASYNC16(bd + l * 16, Bg + l * 8);
    };

    int nc = K / BK;
    issue(0, 0); CP_COMMIT();
    if (nc > 1) { issue(1, 1); CP_COMMIT(); }
    for (int c = 0; c < nc; ++c) {
        if (c + 2 < nc)      { issue(c + 2, (c + 2) % NSTAGE); CP_COMMIT(); CP_WAIT2(); }
        else if (c + 1 < nc) { CP_WAIT1(); }
        else                 { CP_WAIT0(); }
        __syncthreads();
        const __half* As = smem + S_A(c % NSTAGE);
        const __half* Bs = smem + S_B(c % NSTAGE);
#pragma unroll
        for (int ks = 0; ks < BK / 16; ++ks) {
            wmma::fragment<wmma::matrix_a, 16, 16, 16, __half, wmma::row_major> af[4];
            wmma::fragment<wmma::matrix_b, 16, 16, 16, __half, wmma::col_major> bf[2];
#pragma unroll
            for (int i = 0; i < 4; ++i)
                wmma::load_matrix_sync(af[i], As + (wm * 64 + i * 16) * APAD + ks * 16, APAD);
#pragma unroll
            for (int j = 0; j < 2; ++j)
                wmma::load_matrix_sync(bf[j], Bs + (wn * 32 + j * 16) * APAD + ks * 16, APAD);
#pragma unroll
            for (int i = 0; i < 4; ++i)
#pragma unroll
                for (int j = 0; j < 2; ++j)
                    wmma::mma_sync(acc[i][j], af[i], bf[j], acc[i][j]);
        }
        __syncthreads();
    }

    // ---- epilogue: stage accumulators through smem (fp32), then elementwise ----
    float* Ct = reinterpret_cast<float*>(smem);   // 128x128 = 64KB <= 108KB
#pragma unroll
    for (int i = 0; i < 4; ++i)
#pragma unroll
        for (int j = 0; j < 2; ++j)
            wmma::store_matrix_sync(Ct + (wm * 64 + i * 16) * BN + wn * 32 + j * 16,
                                    acc[i][j], BN, wmma::mem_row_major);
    __syncthreads();

    int r = t >> 1;                 // row 0..127
    int ch = (t & 1) * 64;          // column half
    const float* srow = Ct + r * BN + ch;
    if (MODE == 1) {
        __half* crow = (__half*)Cb + (size_t)(m0 + r) * ldc + n0 + ch;
        float rowsum = 0.f;
#pragma unroll
        for (int j = 0; j < 64; j += 8) {
            float4 v0 = *(const float4*)(srow + j);
            float4 v1 = *(const float4*)(srow + j + 4);
            float e0 = __expf(alpha * v0.x), e1 = __expf(alpha * v0.y);
            float e2 = __expf(alpha * v0.z), e3 = __expf(alpha * v0.w);
            float e4 = __expf(alpha * v1.x), e5 = __expf(alpha * v1.y);
            float e6 = __expf(alpha * v1.z), e7 = __expf(alpha * v1.w);
            rowsum += ((e0 + e1) + (e2 + e3)) + ((e4 + e5) + (e6 + e7));
            uint4 pkd;
            pkd.x = pack2(e0, e1); pkd.y = pack2(e2, e3);
            pkd.z = pack2(e4, e5); pkd.w = pack2(e6, e7);
            *(uint4*)(crow + j) = pkd;
        }
        rowsum += __shfl_xor_sync(0xffffffffu, rowsum, 1);
        if ((t & 1) == 0)
            lpart[((size_t)z * QQ + m0 + r) * NTILES + blockIdx.x] = rowsum;
    } else {
        OutT* crow = Cb + (size_t)(m0 + r) * ldc + n0 + ch;
#pragma unroll
        for (int j = 0; j < 64; j += 4) {
            float4 v = *(const float4*)(srow + j);
            float b0 = 0.f, b1 = 0.f, b2 = 0.f, b3 = 0.f;
            if (biasb) {
                const float* bp = biasb + n0 + ch + j;
                b0 = bp[0]; b1 = bp[1]; b2 = bp[2]; b3 = bp[3];
            }
            v.x = alpha * v.x + b0; v.y = alpha * v.y + b1;
            v.z = alpha * v.z + b2; v.w = alpha * v.w + b3;
            if (sizeof(OutT) == 2) {
                uint2 pkd; pkd.x = pack2(v.x, v.y); pkd.y = pack2(v.z, v.w);
                *(uint2*)(crow + j) = pkd;
            } else {
                *(float4*)((float*)crow + j) = v;
            }
        }
    }
}

// ---------------- K: head-average of exp'd fp16 scores -> fp16 attn ----------
// attn[b][i][j] = (1/16) * sum_h escore[bh][i][j] / l[bh][i]
__global__ void __launch_bounds__(256) attn_avg() {
    int blk = blockIdx.x;
    int b = blk >> 11, i = blk & 2047;
    int t = threadIdx.x;
    __shared__ float il_s[16];
    if (t < 16) {
        const float* lp = g_lpart + ((size_t)(b * 16 + t) * QQ + i) * NTILES;
        float s = 0.f;
#pragma unroll
        for (int j = 0; j < NTILES; ++j) s += lp[j];
        il_s[t] = 1.0f / s;
    }
    __syncthreads();
    float acc[8];
#pragma unroll
    for (int j = 0; j < 8; ++j) acc[j] = 0.f;
    for (int h = 0; h < 16; ++h) {
        const __half* p = g_scores + ((size_t)(b * 16 + h) * QQ + i) * KVN + t * 8;
        float il = il_s[h];
        uint4 raw = *(const uint4*)p;
        float2 f0 = __half22float2(*reinterpret_cast<__half2*>(&raw.x));
        float2 f1 = __half22float2(*reinterpret_cast<__half2*>(&raw.y));
        float2 f2 = __half22float2(*reinterpret_cast<__half2*>(&raw.z));
        float2 f3 = __half22float2(*reinterpret_cast<__half2*>(&raw.w));
        acc[0] += f0.x * il; acc[1] += f0.y * il;
        acc[2] += f1.x * il; acc[3] += f1.y * il;
        acc[4] += f2.x * il; acc[5] += f2.y * il;
        acc[6] += f3.x * il; acc[7] += f3.y * il;
    }
    __half* o = g_attn + ((size_t)b * QQ + i) * KVN + t * 8;
    uint4 pkd;
    pkd.x = pack2(acc[0] * 0.0625f, acc[1] * 0.0625f);
    pkd.y = pack2(acc[2] * 0.0625f, acc[3] * 0.0625f);
    pkd.z = pack2(acc[4] * 0.0625f, acc[5] * 0.0625f);
    pkd.w = pack2(acc[6] * 0.0625f, acc[7] * 0.0625f);
    *(uint4*)o = pkd;
}

// ---------------- launch -----------------------------------------------------
extern "C" void kernel_launch(void* const* d_in, const int* in_sizes, int n_in,
                              void* d_out, int out_size) {
    const float* query   = (const float*)d_in[0];
    const float* key     = (const float*)d_in[1];
    const float* value   = (const float*)d_in[2];
    const float* wq_norm = (const float*)d_in[3];
    const float* wk_norm = (const float*)d_in[4];
    const float* Wq      = (const float*)d_in[5];
    const float* Wk      = (const float*)d_in[6];
    const float* bq      = (const float*)d_in[7];
    const float* bk      = (const float*)d_in[8];
    float* out = (float*)d_out;

    __half *xn, *Wr, *qkp, *vT, *attn, *scores;
    float *bvec, *lpart;
    cudaGetSymbolAddress((void**)&xn, g_xn);
    cudaGetSymbolAddress((void**)&Wr, g_Wr);
    cudaGetSymbolAddress((void**)&bvec, g_b);
    cudaGetSymbolAddress((void**)&qkp, g_qkp);
    cudaGetSymbolAddress((void**)&vT, g_vT);
    cudaGetSymbolAddress((void**)&scores, g_scores);
    cudaGetSymbolAddress((void**)&lpart, g_lpart);
    cudaGetSymbolAddress((void**)&attn, g_attn);

    cudaFuncSetAttribute((const void*)gemm_mma<0, __half>,
                         cudaFuncAttributeMaxDynamicSharedMemorySize, SMEM_BYTES);
    cudaFuncSetAttribute((const void*)gemm_mma<0, float>,
                         cudaFuncAttributeMaxDynamicSharedMemorySize, SMEM_BYTES);
    cudaFuncSetAttribute((const void*)gemm_mma<1, __half>,
                         cudaFuncAttributeMaxDynamicSharedMemorySize, SMEM_BYTES);

    // prep
    rmsnorm_fold<<<dim3(MROWS, 2), 256>>>(query, key, wq_norm, wk_norm);
    wprep<<<dim3(DD * DD / 1024, 2), 256>>>(Wq, Wk, bq, bk);
    transpose_v<<<dim3(KVN / 32, DD / 32, BB), dim3(32, 8)>>>(value);

    // merged projections: qkp[z] = xn[z] @ Wr[z]^T + b[z]  (M=4096,N=1024,K=1024) x2
    gemm_mma<0, __half><<<dim3(DD / BN, MROWS / BM, 2), 256, SMEM_BYTES>>>(
        xn, Wr, bvec, qkp, nullptr, DD, DD, DD, DD,
        (long)MROWS * DD, (long)DD * DD, (long)MROWS * DD, DD, 1.0f);

    // scores: escore[bh] = exp(0.125 * qp_h @ kp_h^T) fp16  (M=2048,N=2048,K=64) x32
    gemm_mma<1, __half><<<dim3(KVN / BN, QQ / BM, BB * HH), 256, SMEM_BYTES>>>(
        qkp, qkp + (size_t)MROWS * DD, nullptr, scores, lpart, 64, DD, DD, KVN,
        (long)QQ * DD, (long)QQ * DD, (long)QQ * KVN, 0, 0.125f);

    // softmax normalize + head average -> fp16 attn
    attn_avg<<<BB * QQ, 256>>>();

    // out = attn @ value  (M=2048, N=1024, K=2048) x2 -> fp32
    gemm_mma<0, float><<<dim3(DD / BN, QQ / BM, BB), 256, SMEM_BYTES>>>(
        attn, vT, nullptr, out, nullptr, KVN, KVN, KVN, DD,
        (long)QQ * KVN, (long)DD * KVN, (long)QQ * DD, 0, 1.0f);
}

// round 16
// speedup vs baseline: 1.1298x; 1.1298x over previous
#include <cuda_runtime.h>
#include <cuda_fp16.h>
#include <mma.h>
#include <cstdint>

using namespace nvcuda;

// Problem constants: B=2, Q=KV=2048, D=1024, H=16, DH=64
#define BB     2
#define QQ     2048
#define KVN    2048
#define DD     1024
#define HH     16
#define MROWS  (BB*QQ)
#define EPS_F  1.1920928955078125e-07f

// GEMM tiling (fp16 operands, fp32 accum): 256 thr, 2x4 warps, warp tile 64x32
#define BM 128
#define BN 128
#define BK 64                    // 64 halves = 128B per row slab
#define APAD 72                  // padded row stride in halves
#define NTILES (KVN / BN)        // 16 n-tiles for scores lpart
#define NJ 4                     // scores: j-subtiles per CTA

// main GEMM smem (R7 layout): As[2][128*72] | Bs[2][128*72]; epilogue reuses as float C
#define S_A(buf)  ((buf) * (BM * APAD))
#define S_B(buf)  (2 * BM * APAD + (buf) * (BN * APAD))
#define SMEM_HALVES (4 * BM * APAD)
#define SMEM_BYTES  (SMEM_HALVES * 2)          // 73728

// scores kernel smem (bytes): A 18432 | B0 18432 | B1 18432 | Ct 32768
#define SC_B_OFF   18432
#define SC_BSTR    18432
#define SC_CT_OFF  55296
#define SC_SMEM    88064

// ---------------- scratch ----------------------------------------------------
__device__ __half g_qn[(size_t)MROWS * DD];
__device__ __half g_kn[(size_t)MROWS * DD];
__device__ __half g_Wqr[(size_t)DD * DD];
__device__ __half g_Wkr[(size_t)DD * DD];
__device__ __half g_qp[(size_t)MROWS * DD];
__device__ __half g_kp[(size_t)MROWS * DD];
__device__ __half g_vT[(size_t)BB * DD * KVN];
__device__ __half g_scores[(size_t)BB * HH * QQ * KVN];   // exp(s/8), fp16 (268MB)
__device__ float  g_lpart[(size_t)BB * HH * QQ * NTILES]; // per-n-tile row sums
__device__ __half g_attn[(size_t)BB * QQ * KVN];

// ---------------- helpers ----------------------------------------------------
__device__ __forceinline__ uint32_t smem_u32(const void* p) {
    uint32_t a;
    asm("{ .reg .u64 t; cvta.to.shared.u64 t, %1; cvt.u32.u64 %0, t; }" : "=r"(a) : "l"(p));
    return a;
}
#define CP_ASYNC16(dst_u32, src_ptr) \
    asm volatile("cp.async.ca.shared.global [%0], [%1], 16;" :: "r"(dst_u32), "l"(src_ptr))
#define CP_COMMIT() asm volatile("cp.async.commit_group;")
#define CP_WAIT1()  asm volatile("cp.async.wait_group 1;")
#define CP_WAIT0()  asm volatile("cp.async.wait_group 0;")

__device__ __forceinline__ uint32_t pack2(float a, float b) {
    __half2 h = __floats2half2_rn(a, b);
    return *reinterpret_cast<uint32_t*>(&h);
}

// ---------------- K: rmsnorm + fold norm-weight -> fp16 ----------------------
__global__ void rmsnorm_fold(const float* __restrict__ q, const float* __restrict__ k,
                             const float* __restrict__ wq, const float* __restrict__ wk) {
    const float* x; const float* w; __half* o;
    if (blockIdx.y == 0) { x = q; w = wq; o = g_qn; } else { x = k; w = wk; o = g_kn; }
    size_t row = blockIdx.x;
    int t = threadIdx.x;
    const float* xr = x + row * DD;
    float4 v = *(const float4*)(xr + t * 4);
    float ss = v.x*v.x + v.y*v.y + v.z*v.z + v.w*v.w;
#pragma unroll
    for (int s = 16; s; s >>= 1) ss += __shfl_xor_sync(0xffffffffu, ss, s);
    __shared__ float red[8];
    if ((t & 31) == 0) red[t >> 5] = ss;
    __syncthreads();
    float tot = 0.f;
#pragma unroll
    for (int i = 0; i < 8; ++i) tot += red[i];
    float sc = rsqrtf(tot * (1.0f / (float)DD) + EPS_F);
    float4 wv = *(const float4*)(w + t * 4);
    uint2 pkd;
    pkd.x = pack2(v.x * sc * wv.x, v.y * sc * wv.y);
    pkd.y = pack2(v.z * sc * wv.z, v.w * sc * wv.w);
    *(uint2*)(o + row * DD + t * 4) = pkd;
}

// ---------------- K: convert projection weights to fp16 ----------------------
__global__ void wprep(const float* __restrict__ Wq, const float* __restrict__ Wk) {
    const float* s = blockIdx.y ? Wk : Wq;
    __half* o = blockIdx.y ? g_Wkr : g_Wqr;
    size_t i = (size_t)blockIdx.x * 1024 + threadIdx.x * 4;
    float4 v = *(const float4*)(s + i);
    uint2 pkd;
    pkd.x = pack2(v.x, v.y);
    pkd.y = pack2(v.z, v.w);
    *(uint2*)(o + i) = pkd;
}

// ---------------- K: transpose value -> vT[b][d][j] fp16 ---------------------
__global__ void transpose_v(const float* __restrict__ v) {
    int b = blockIdx.z;
    int j0 = blockIdx.x * 32, d0 = blockIdx.y * 32;
    __shared__ float T[32][33];
    int tx = threadIdx.x, ty = threadIdx.y;
    const float* src = v + ((size_t)b * KVN + j0) * DD + d0;
#pragma unroll
    for (int e = 0; e < 4; ++e)
        T[ty + 8*e][tx] = src[(size_t)(ty + 8*e) * DD + tx];
    __syncthreads();
    __half* dst = g_vT + ((size_t)b * DD + d0) * KVN + j0;
#pragma unroll
    for (int e = 0; e < 4; ++e)
        dst[(size_t)(ty + 8*e) * KVN + tx] = __float2half_rn(T[tx][ty + 8*e]);
}

// ---------------- fp16 wmma GEMM (R7: 8 warps, 64x32 tiles, 2-stage) ---------
// D[M,N] = alpha * A[M,K] @ B[N,K]^T + bias, A/B fp16 row-major, acc fp32
template <typename OutT>
__global__ void __launch_bounds__(256, 2) gemm_mma(
    const __half* __restrict__ A, const __half* __restrict__ B,
    const float* __restrict__ bias, OutT* __restrict__ C,
    int K, int lda, int ldb, int ldc,
    long aStride, long bStride, long cStride, float alpha) {
    extern __shared__ __half smem[];
    uint32_t sb = smem_u32(smem);
    int t = threadIdx.x, warp = t >> 5;
    int wm = warp >> 2, wn = warp & 3;    // 2 x 4 warp grid; warp tile 64 x 32

    long z = blockIdx.z;
    const __half* Ab = A + z * aStride;
    const __half* Bb = B + z * bStride;
    OutT* Cb = C + z * cStride;
    int m0 = blockIdx.y * BM, n0 = blockIdx.x * BN;

    wmma::fragment<wmma::accumulator, 16, 16, 16, float> acc[4][2];
#pragma unroll
    for (int i = 0; i < 4; ++i)
#pragma unroll
        for (int j = 0; j < 2; ++j) wmma::fill_fragment(acc[i][j], 0.0f);

    int r0 = t >> 1;             // row 0..127
    int cb = (t & 1) * 32;       // half-column base

    auto issue = [&](int c, int buf) {
        const __half* Ag = Ab + (size_t)(m0 + r0) * lda + c * BK + cb;
        const __half* Bg = Bb + (size_t)(n0 + r0) * ldb + c * BK + cb;
        uint32_t ad = sb + (S_A(buf) + r0 * APAD + cb) * 2;
        uint32_t bd = sb + (S_B(buf) + r0 * APAD + cb) * 2;
#pragma unroll
        for (int l = 0; l < 4; ++l) CP_ASYNC16(ad + l * 16, Ag + l * 8);
#pragma unroll
        for (int l = 0; l < 4; ++l) CP_ASYNC16(bd + l * 16, Bg + l * 8);
    };

    int nc = K / BK;
    issue(0, 0); CP_COMMIT();
    for (int c = 0; c < nc; ++c) {
        if (c + 1 < nc) { issue(c + 1, (c + 1) & 1); CP_COMMIT(); CP_WAIT1(); }
        else           { CP_WAIT0(); }
        __syncthreads();
        const __half* As = smem + S_A(c & 1);
        const __half* Bs = smem + S_B(c & 1);
#pragma unroll
        for (int ks = 0; ks < BK / 16; ++ks) {
            wmma::fragment<wmma::matrix_a, 16, 16, 16, __half, wmma::row_major> af[4];
            wmma::fragment<wmma::matrix_b, 16, 16, 16, __half, wmma::col_major> bf[2];
#pragma unroll
            for (int i = 0; i < 4; ++i)
                wmma::load_matrix_sync(af[i], As + (wm * 64 + i * 16) * APAD + ks * 16, APAD);
#pragma unroll
            for (int j = 0; j < 2; ++j)
                wmma::load_matrix_sync(bf[j], Bs + (wn * 32 + j * 16) * APAD + ks * 16, APAD);
#pragma unroll
            for (int i = 0; i < 4; ++i)
#pragma unroll
                for (int j = 0; j < 2; ++j)
                    wmma::mma_sync(acc[i][j], af[i], bf[j], acc[i][j]);
        }
        __syncthreads();
    }

    // epilogue via smem fp32 staging
    float* Ct = reinterpret_cast<float*>(smem);   // 128x128 = 64KB
#pragma unroll
    for (int i = 0; i < 4; ++i)
#pragma unroll
        for (int j = 0; j < 2; ++j)
            wmma::store_matrix_sync(Ct + (wm * 64 + i * 16) * BN + wn * 32 + j * 16,
                                    acc[i][j], BN, wmma::mem_row_major);
    __syncthreads();

    int r = t >> 1;
    int ch = (t & 1) * 64;
    const float* srow = Ct + r * BN + ch;
    OutT* crow = Cb + (size_t)(m0 + r) * ldc + n0 + ch;
#pragma unroll
    for (int j = 0; j < 64; j += 4) {
        float4 v = *(const float4*)(srow + j);
        float b0 = 0.f, b1 = 0.f, b2 = 0.f, b3 = 0.f;
        if (bias) {
            const float* bp = bias + n0 + ch + j;
            b0 = bp[0]; b1 = bp[1]; b2 = bp[2]; b3 = bp[3];
        }
        v.x = alpha * v.x + b0; v.y = alpha * v.y + b1;
        v.z = alpha * v.z + b2; v.w = alpha * v.w + b3;
        if (sizeof(OutT) == 2) {
            uint2 pkd; pkd.x = pack2(v.x, v.y); pkd.y = pack2(v.z, v.w);
            *(uint2*)(crow + j) = pkd;
        } else {
            *(float4*)((float*)crow + j) = v;
        }
    }
}

// ---------------- scores kernel: NJ j-subtiles per CTA, A reused -------------
// escore[bh][i][j] = exp(0.125 * qp_h[i,:] . kp_h[j,:]), fp16; fp32 rowsums -> lpart
__global__ void __launch_bounds__(256, 2) scores_mma(
    const __half* __restrict__ Ag0, const __half* __restrict__ Bg0,
    __half* __restrict__ C, float* __restrict__ lpart) {
    extern __shared__ __half smem[];
    uint32_t sb = smem_u32(smem);
    int t = threadIdx.x, warp = t >> 5;
    int wm = warp >> 2, wn = warp & 3;    // 2x4 warp grid; warp tile 64x32

    long z = blockIdx.z;
    long b = z >> 4, h = z & 15;
    const __half* Ab = Ag0 + b * (long)QQ * DD + h * 64;
    const __half* Bb = Bg0 + b * (long)KVN * DD + h * 64;
    __half* Cb = C + z * (long)QQ * KVN;
    int m0 = blockIdx.y * BM;
    int n00 = blockIdx.x * (BN * NJ);

    int r0 = t >> 1;             // row 0..127
    int cb2 = (t & 1) * 32;

    // load A tile once (128 x 64 halves)
    {
        const __half* Ag = Ab + (size_t)(m0 + r0) * DD + cb2;
        uint32_t ad = sb + (r0 * APAD + cb2) * 2;
#pragma unroll
        for (int l = 0; l < 4; ++l) CP_ASYNC16(ad + l * 16, Ag + l * 8);
        CP_COMMIT();
    }
    auto issueB = [&](int jt) {
        const __half* Bg = Bb + (size_t)(n00 + jt * BN + r0) * DD + cb2;
        uint32_t bd = sb + SC_B_OFF + (jt & 1) * SC_BSTR + (r0 * APAD + cb2) * 2;
#pragma unroll
        for (int l = 0; l < 4; ++l) CP_ASYNC16(bd + l * 16, Bg + l * 8);
        CP_COMMIT();
    };
    issueB(0); issueB(1);

    float* Ct = reinterpret_cast<float*>(reinterpret_cast<char*>(smem) + SC_CT_OFF); // 64x128

    for (int jt = 0; jt < NJ; ++jt) {
        if (jt < NJ - 1) CP_WAIT1(); else CP_WAIT0();
        __syncthreads();

        wmma::fragment<wmma::accumulator, 16, 16, 16, float> acc[4][2];
#pragma unroll
        for (int i = 0; i < 4; ++i)
#pragma unroll
            for (int j = 0; j < 2; ++j) wmma::fill_fragment(acc[i][j], 0.0f);

        const __half* As = smem;
        const __half* Bs = smem + (SC_B_OFF + (jt & 1) * SC_BSTR) / 2;
#pragma unroll
        for (int ks = 0; ks < BK / 16; ++ks) {
            wmma::fragment<wmma::matrix_a, 16, 16, 16, __half, wmma::row_major> af[4];
            wmma::fragment<wmma::matrix_b, 16, 16, 16, __half, wmma::col_major> bf[2];
#pragma unroll
            for (int i = 0; i < 4; ++i)
                wmma::load_matrix_sync(af[i], As + (wm * 64 + i * 16) * APAD + ks * 16, APAD);
#pragma unroll
            for (int j = 0; j < 2; ++j)
                wmma::load_matrix_sync(bf[j], Bs + (wn * 32 + j * 16) * APAD + ks * 16, APAD);
#pragma unroll
            for (int i = 0; i < 4; ++i)
#pragma unroll
                for (int j = 0; j < 2; ++j)
                    wmma::mma_sync(acc[i][j], af[i], bf[j], acc[i][j]);
        }
        __syncthreads();                  // all warps done reading B[jt&1]
        if (jt + 2 < NJ) issueB(jt + 2);  // refill consumed buffer

        int nbase = n00 + jt * BN;
        // two-pass epilogue through 64x128 Ct
#pragma unroll
        for (int pass = 0; pass < 2; ++pass) {
            if (wm == pass) {
#pragma unroll
                for (int i = 0; i < 4; ++i)
#pragma unroll
                    for (int j = 0; j < 2; ++j)
                        wmma::store_matrix_sync(Ct + (i * 16) * BN + wn * 32 + j * 16,
                                                acc[i][j], BN, wmma::mem_row_major);
            }
            __syncthreads();
            int r = t >> 2;               // 0..63
            int c0 = (t & 3) * 32;
            const float* srow = Ct + r * BN + c0;
            int grow = m0 + pass * 64 + r;
            __half* crow = Cb + (size_t)grow * KVN + nbase + c0;
            float rs = 0.f;
#pragma unroll
            for (int j = 0; j < 32; j += 8) {
                float4 v0 = *(const float4*)(srow + j);
                float4 v1 = *(const float4*)(srow + j + 4);
                float e0 = __expf(0.125f * v0.x), e1 = __expf(0.125f * v0.y);
                float e2 = __expf(0.125f * v0.z), e3 = __expf(0.125f * v0.w);
                float e4 = __expf(0.125f * v1.x), e5 = __expf(0.125f * v1.y);
                float e6 = __expf(0.125f * v1.z), e7 = __expf(0.125f * v1.w);
                rs += ((e0 + e1) + (e2 + e3)) + ((e4 + e5) + (e6 + e7));
                uint4 pkd;
                pkd.x = pack2(e0, e1); pkd.y = pack2(e2, e3);
                pkd.z = pack2(e4, e5); pkd.w = pack2(e6, e7);
                *(uint4*)(crow + j) = pkd;
            }
            rs += __shfl_xor_sync(0xffffffffu, rs, 1);
            rs += __shfl_xor_sync(0xffffffffu, rs, 2);
            if ((t & 3) == 0)
                lpart[((size_t)z * QQ + grow) * NTILES + blockIdx.x * NJ + jt] = rs;
            __syncthreads();              // Ct free for next pass / jt
        }
    }
}

// ---------------- K: head-average of exp'd fp16 scores -> fp16 attn ----------
__global__ void __launch_bounds__(256) attn_avg() {
    int blk = blockIdx.x;
    int b = blk >> 11, i = blk & 2047;
    int t = threadIdx.x;
    __shared__ float il_s[16];
    if (t < 16) {
        const float* lp = g_lpart + ((size_t)(b * 16 + t) * QQ + i) * NTILES;
        float s = 0.f;
#pragma unroll
        for (int j = 0; j < NTILES; ++j) s += lp[j];
        il_s[t] = 1.0f / s;
    }
    __syncthreads();
    float acc[8];
#pragma unroll
    for (int j = 0; j < 8; ++j) acc[j] = 0.f;
    for (int h = 0; h < 16; ++h) {
        const __half* p = g_scores + ((size_t)(b * 16 + h) * QQ + i) * KVN + t * 8;
        float il = il_s[h];
        uint4 raw = *(const uint4*)p;
        float2 f0 = __half22float2(*reinterpret_cast<__half2*>(&raw.x));
        float2 f1 = __half22float2(*reinterpret_cast<__half2*>(&raw.y));
        float2 f2 = __half22float2(*reinterpret_cast<__half2*>(&raw.z));
        float2 f3 = __half22float2(*reinterpret_cast<__half2*>(&raw.w));
        acc[0] += f0.x * il; acc[1] += f0.y * il;
        acc[2] += f1.x * il; acc[3] += f1.y * il;
        acc[4] += f2.x * il; acc[5] += f2.y * il;
        acc[6] += f3.x * il; acc[7] += f3.y * il;
    }
    __half* o = g_attn + ((size_t)b * QQ + i) * KVN + t * 8;
    uint4 pkd;
    pkd.x = pack2(acc[0] * 0.0625f, acc[1] * 0.0625f);
    pkd.y = pack2(acc[2] * 0.0625f, acc[3] * 0.0625f);
    pkd.z = pack2(acc[4] * 0.0625f, acc[5] * 0.0625f);
    pkd.w = pack2(acc[6] * 0.0625f, acc[7] * 0.0625f);
    *(uint4*)o = pkd;
}

// ---------------- launch -----------------------------------------------------
extern "C" void kernel_launch(void* const* d_in, const int* in_sizes, int n_in,
                              void* d_out, int out_size) {
    const float* query   = (const float*)d_in[0];
    const float* key     = (const float*)d_in[1];
    const float* value   = (const float*)d_in[2];
    const float* wq_norm = (const float*)d_in[3];
    const float* wk_norm = (const float*)d_in[4];
    const float* Wq      = (const float*)d_in[5];
    const float* Wk      = (const float*)d_in[6];
    const float* bq      = (const float*)d_in[7];
    const float* bk      = (const float*)d_in[8];
    float* out = (float*)d_out;

    __half *qn, *kn, *Wqr, *Wkr, *qp, *kp, *vT, *attn, *scores;
    float *lpart;
    cudaGetSymbolAddress((void**)&qn, g_qn);
    cudaGetSymbolAddress((void**)&kn, g_kn);
    cudaGetSymbolAddress((void**)&Wqr, g_Wqr);
    cudaGetSymbolAddress((void**)&Wkr, g_Wkr);
    cudaGetSymbolAddress((void**)&qp, g_qp);
    cudaGetSymbolAddress((void**)&kp, g_kp);
    cudaGetSymbolAddress((void**)&vT, g_vT);
    cudaGetSymbolAddress((void**)&scores, g_scores);
    cudaGetSymbolAddress((void**)&lpart, g_lpart);
    cudaGetSymbolAddress((void**)&attn, g_attn);

    cudaFuncSetAttribute((const void*)gemm_mma<__half>,
                         cudaFuncAttributeMaxDynamicSharedMemorySize, SMEM_BYTES);
    cudaFuncSetAttribute((const void*)gemm_mma<float>,
                         cudaFuncAttributeMaxDynamicSharedMemorySize, SMEM_BYTES);
    cudaFuncSetAttribute((const void*)scores_mma,
                         cudaFuncAttributeMaxDynamicSharedMemorySize, SC_SMEM);

    // prep
    rmsnorm_fold<<<dim3(MROWS, 2), 256>>>(query, key, wq_norm, wk_norm);
    wprep<<<dim3(DD * DD / 1024, 2), 256>>>(Wq, Wk);
    transpose_v<<<dim3(KVN / 32, DD / 32, BB), dim3(32, 8)>>>(value);

    // projections: qp = qn @ Wq^T + bq  (M=4096, N=1024, K=1024) -> fp16
    gemm_mma<__half><<<dim3(DD / BN, MROWS / BM, 1), 256, SMEM_BYTES>>>(
        qn, Wqr, bq, qp, DD, DD, DD, DD, 0, 0, 0, 1.0f);
    gemm_mma<__half><<<dim3(DD / BN, MROWS / BM, 1), 256, SMEM_BYTES>>>(
        kn, Wkr, bk, kp, DD, DD, DD, DD, 0, 0, 0, 1.0f);

    // scores: 2048 CTAs, each 128x512 output with A reuse
    scores_mma<<<dim3(KVN / (BN * NJ), QQ / BM, BB * HH), 256, SC_SMEM>>>(
        qp, kp, scores, lpart);

    // softmax normalize + head average -> fp16 attn
    attn_avg<<<BB * QQ, 256>>>();

    // out = attn @ value  (M=2048, N=1024, K=2048) x2 -> fp32
    gemm_mma<float><<<dim3(DD / BN, QQ / BM, BB), 256, SMEM_BYTES>>>(
        attn, vT, nullptr, out, KVN, KVN, KVN, DD,
        (long)QQ * KVN, (long)DD * KVN, (long)QQ * DD, 1.0f);
}